// round 9
// baseline (speedup 1.0000x reference)
#include <cuda_runtime.h>
#include <stdint.h>

// EarthMoversDistanceRegularizer v8: persistent fused onesweep segmented LSD
// radix sort (pass-major tickets, per-segment pass gating). vs v7:
//   - IT 8->10 (TILE 5120): ~18% fewer tiles -> less per-tile overhead
//   - next-pass histogram match-aggregated in writeout loop for skewed
//     passes 1-2 (bytes 2,3); pass 0 (uniform byte 1) keeps plain atomics
//   - k_offsets+k_toff merged into k_setup

#define NSEG     200
#define NMAX     8388608
#define NT       512
#define NWARP    16
#define IT       10
#define TILE     (NT * IT)              // 5120
#define MAXT     1840                   // >= NMAX/TILE + NSEG = 1839
#define GRIDSORT 444
#define FULLMASK 0xffffffffu
#define FLAGBIT  (1u << 30)
#define CNTMASK  0x3fffffffu

__device__ uint32_t g_keyA[NMAX];
__device__ uint32_t g_keyB[NMAX];
__device__ int      g_off[NSEG + 1];
__device__ int      g_toff[NSEG + 1];
__device__ int      g_tseg[MAXT];
__device__ uint32_t g_hist[NSEG][4][256];
__device__ uint32_t g_status[4][MAXT][256];
__device__ uint32_t g_segdone[3][NSEG];
__device__ uint32_t g_ticket;
__device__ float    g_part[MAXT];

__device__ __forceinline__ uint32_t flipf(uint32_t u) {
    return (u & 0x80000000u) ? ~u : (u | 0x80000000u);
}
__device__ __forceinline__ float unflip(uint32_t k) {
    uint32_t u = (k & 0x80000000u) ? (k & 0x7fffffffu) : ~k;
    return __uint_as_float(u);
}
__device__ __forceinline__ void st_rlx(uint32_t* p, uint32_t v) {
    asm volatile("st.relaxed.gpu.u32 [%0], %1;" :: "l"(p), "r"(v) : "memory");
}
__device__ __forceinline__ uint32_t ld_rlx(const uint32_t* p) {
    uint32_t v;
    asm volatile("ld.relaxed.gpu.u32 %0, [%1];" : "=r"(v) : "l"(p) : "memory");
    return v;
}
__device__ __forceinline__ uint32_t ld_acq(const uint32_t* p) {
    uint32_t v;
    asm volatile("ld.acquire.gpu.u32 %0, [%1];" : "=r"(v) : "l"(p) : "memory");
    return v;
}

struct SortSmem {
    uint32_t cnt[256][17];   // padded: conflict-free rank atomics + scan
    uint32_t exch[TILE];
    uint32_t loc[256];
    uint32_t fix[256];
    uint32_t wsum[8];
    uint32_t h[4][256];
    float    red[NWARP];
    int      tk;
};

// ---------------------------------------------------------------------------
// Exclusive prefix over values held by threads 0..255 (others pass 0).
// All threads of the block must call (contains barriers).
__device__ __forceinline__ uint32_t scan256(uint32_t v, int tid, uint32_t* s_wsum) {
    int lane = tid & 31, w = tid >> 5;
    uint32_t inc = v;
#pragma unroll
    for (int o = 1; o < 32; o <<= 1) {
        uint32_t t = __shfl_up_sync(FULLMASK, inc, o);
        if (lane >= o) inc += t;
    }
    if (lane == 31 && w < 8) s_wsum[w] = inc;
    __syncthreads();
    if (w == 0 && lane < 8) {
        uint32_t x0 = s_wsum[lane];
        uint32_t i2 = x0;
#pragma unroll
        for (int o = 1; o < 8; o <<= 1) {
            uint32_t t = __shfl_up_sync(0xffu, i2, o);
            if (lane >= o) i2 += t;
        }
        s_wsum[lane] = i2 - x0;
    }
    __syncthreads();
    return inc - v + ((tid < 256) ? s_wsum[w] : 0u);
}

// ---------------------------------------------------------------------------
// Segment offsets (binary search) + tile offsets + tile->segment map.
__global__ void k_setup(const int* __restrict__ seg, int n) {
    __shared__ uint32_t s_wsum[8];
    int tid = threadIdx.x;
    if (tid <= NSEG) {
        int lo = 0, hi = n;
        while (lo < hi) {
            int mid = (lo + hi) >> 1;
            if (seg[mid] < tid) lo = mid + 1; else hi = mid;
        }
        g_off[tid] = lo;
    }
    __syncthreads();
    uint32_t nt = 0;
    if (tid < NSEG) {
        int len = g_off[tid + 1] - g_off[tid];
        nt = (uint32_t)((len + TILE - 1) / TILE);
    }
    uint32_t excl = scan256(nt, tid, s_wsum);
    if (tid <= NSEG) g_toff[tid] = (int)excl;
    for (int t = tid; t < MAXT; t += 256) g_tseg[t] = -1;
    __syncthreads();
    if (tid < NSEG)
        for (uint32_t t = 0; t < nt; t++) g_tseg[excl + t] = tid;
}

// ---------------------------------------------------------------------------
__global__ void k_zero() {
    const int gtid = blockIdx.x * blockDim.x + threadIdx.x;
    const int gstr = gridDim.x * blockDim.x;
    uint32_t* p = &g_status[0][0][0];
    for (int i = gtid; i < 4 * MAXT * 256; i += gstr) p[i] = 0;
    uint32_t* h = &g_hist[0][0][0];
    for (int i = gtid; i < NSEG * 4 * 256; i += gstr) h[i] = 0;
    uint32_t* d = &g_segdone[0][0];
    for (int i = gtid; i < 3 * NSEG; i += gstr) d[i] = 0;
    if (gtid == 0) g_ticket = 0;
}

// ---------------------------------------------------------------------------
// Pass-0 (low byte) per-segment histogram; keys re-derived on the fly by
// pass 0 of k_sort. Low mantissa byte ~uniform -> spread smem atomics.
__global__ __launch_bounds__(NT) void k_hist0(const float* __restrict__ x) {
    __shared__ uint32_t s_h[4][256];
    const int b = blockIdx.x;
    const int s = g_tseg[b];
    if (s < 0) return;
    const int tid = threadIdx.x, rep = (tid >> 5) & 3;

    const int t    = b - g_toff[s];
    const int tbeg = g_off[s] + t * TILE;
    const int tend = min(tbeg + TILE, g_off[s + 1]);

    for (int i = tid; i < 4 * 256; i += NT) ((uint32_t*)s_h)[i] = 0;
    __syncthreads();

    for (int i = tbeg + tid; i < tend; i += NT)
        atomicAdd(&s_h[rep][flipf(__float_as_uint(x[i])) & 255u], 1u);
    __syncthreads();
    if (tid < 256) {
        uint32_t v = s_h[0][tid] + s_h[1][tid] + s_h[2][tid] + s_h[3][tid];
        if (v) atomicAdd(&g_hist[s][0][tid], v);
    }
}

// ---------------------------------------------------------------------------
// One tile of one pass (called from the persistent k_sort).
template <int PASS, bool FUSE>
__device__ __forceinline__ void process_tile(int b,
                                             const float* __restrict__ xin,
                                             const float* __restrict__ init_sorted,
                                             SortSmem& sm) {
    const int s = g_tseg[b];
    const int tid = threadIdx.x, lane = tid & 31, warp = tid >> 5;
    const uint32_t lmask = (1u << lane) - 1u;

    const uint32_t* __restrict__ in =
        (PASS == 1 || PASS == 3) ? g_keyA : g_keyB;   // PASS0 unused
    uint32_t* __restrict__ out = (PASS & 1) ? g_keyB : g_keyA;
    const int shift = 8 * PASS;

    const int beg  = g_off[s], end = g_off[s + 1];
    const int t    = b - g_toff[s];
    const int tbeg = beg + t * TILE;
    const int tend = min(tbeg + TILE, end);
    const int vc   = tend - tbeg;

    // ---- gate: previous pass of this segment must be fully complete
    if (PASS > 0) {
        if (tid == 0) {
            uint32_t need = (uint32_t)(g_toff[s + 1] - g_toff[s]);
            while (ld_acq(&g_segdone[PASS - 1][s]) < need) __nanosleep(64);
        }
        __syncthreads();
    }

    for (int i = tid; i < 256 * 17; i += NT) ((uint32_t*)sm.cnt)[i] = 0;
    if (PASS < 3)
        for (int i = tid; i < 4 * 256; i += NT) ((uint32_t*)sm.h)[i] = 0;
    __syncthreads();

    uint32_t keys[IT];
    uint32_t rnkp[(IT + 1) / 2] = {};   // 2 x u16 ranks per word
    const int ibase = tbeg + warp * (IT * 32) + lane;

    if (vc == TILE) {
        // -------- fast path: every item valid
#pragma unroll
        for (int j = 0; j < IT; j++) {
            int idx = ibase + j * 32;
            keys[j] = (PASS == 0) ? flipf(__float_as_uint(xin[idx])) : in[idx];
        }
#pragma unroll
        for (int j = 0; j < IT; j++) {
            uint32_t d = (keys[j] >> shift) & 255u;
            uint32_t m = __match_any_sync(FULLMASK, d);
            int lead = __ffs(m) - 1;
            uint32_t cur = 0;
            if (lane == lead) cur = atomicAdd(&sm.cnt[d][warp], (uint32_t)__popc(m));
            cur = __shfl_sync(FULLMASK, cur, lead);
            rnkp[j >> 1] |= (cur + (uint32_t)__popc(m & lmask)) << (16 * (j & 1));
        }
    } else {
        // -------- tail tile: masked
#pragma unroll
        for (int j = 0; j < IT; j++) {
            int idx = ibase + j * 32;
            bool valid = idx < tend;
            keys[j] = valid ? ((PASS == 0) ? flipf(__float_as_uint(xin[idx]))
                                           : in[idx])
                            : 0u;
        }
#pragma unroll
        for (int j = 0; j < IT; j++) {
            bool valid = (ibase + j * 32) < tend;
            uint32_t d = (keys[j] >> shift) & 255u;
            uint32_t vm = __ballot_sync(FULLMASK, valid);
            uint32_t m  = __match_any_sync(FULLMASK, d) & vm;
            int lead = m ? (__ffs(m) - 1) : 0;
            uint32_t cur = 0;
            if (valid && lane == lead)
                cur = atomicAdd(&sm.cnt[d][warp], (uint32_t)__popc(m));
            cur = __shfl_sync(FULLMASK, cur, lead);
            rnkp[j >> 1] |= (cur + (uint32_t)__popc(m & lmask)) << (16 * (j & 1));
        }
    }
    __syncthreads();

    // ---- per-digit warp totals -> warp-exclusive in place; publish count
    uint32_t tot = 0;
    if (tid < 256) {
        uint32_t run = 0;
#pragma unroll
        for (int w = 0; w < NWARP; w++) {
            uint32_t c = sm.cnt[tid][w];
            sm.cnt[tid][w] = run;
            run += c;
        }
        tot = run;
        st_rlx(&g_status[PASS][b][tid], tot | FLAGBIT);   // unblock successors
    }

    // ---- packed scan: hi16 = tile-local digit start, lo16 = segment base
    // (cumulative tot <= 5120, cumulative hist <= seg len < 65536: no carry)
    uint32_t h = (tid < 256) ? g_hist[s][PASS][tid] : 0u;
    uint32_t px = scan256((tot << 16) | h, tid, sm.wsum);
    uint32_t loc  = px >> 16;
    uint32_t segx = px & 0xffffu;

    // ---- AGG-only lookback, 4-wide MLP batches
    if (tid < 256) {
        uint32_t excl = 0;
        int pt = b - 1;
        const int first = b - t;
        while (pt >= first) {
            int nb = min(4, pt - first + 1);
            uint32_t v0, v1 = 0, v2 = 0, v3 = 0;
            bool ok;
            do {
                v0 = ld_rlx(&g_status[PASS][pt][tid]);
                if (nb > 1) v1 = ld_rlx(&g_status[PASS][pt - 1][tid]);
                if (nb > 2) v2 = ld_rlx(&g_status[PASS][pt - 2][tid]);
                if (nb > 3) v3 = ld_rlx(&g_status[PASS][pt - 3][tid]);
                ok = (v0 != 0) && (nb < 2 || v1 != 0) &&
                     (nb < 3 || v2 != 0) && (nb < 4 || v3 != 0);
            } while (!ok);
            excl += (v0 & CNTMASK) + (v1 & CNTMASK) +
                    (v2 & CNTMASK) + (v3 & CNTMASK);
            pt -= nb;
        }
        sm.loc[tid] = loc;
        sm.fix[tid] = (uint32_t)beg + segx + excl - loc;
    }
    __syncthreads();

    // ---- scatter to smem exchange by tile-local rank
#pragma unroll
    for (int j = 0; j < IT; j++) {
        int idx = ibase + j * 32;
        if (idx < tend) {
            uint32_t d = (keys[j] >> shift) & 255u;
            uint32_t r = (rnkp[j >> 1] >> (16 * (j & 1))) & 0xffffu;
            sm.exch[sm.loc[d] + sm.cnt[d][warp] + r] = keys[j];
        }
    }
    __syncthreads();

    // ---- coalesced global pass; inline next-pass histogram.
    //      Pass 0 hist digit (byte 1) is ~uniform: plain replicated atomics.
    //      Passes 1-2 hist digits (bytes 2,3) are heavily skewed: match-
    //      aggregate so one leader atomic covers the whole same-digit group.
    float acc = 0.f;
#pragma unroll
    for (int j = 0; j < IT; j++) {
        int p = j * NT + tid;
        bool v = p < vc;
        uint32_t k = v ? sm.exch[p] : 0u;
        if (v) {
            uint32_t d = (k >> shift) & 255u;
            uint32_t g = sm.fix[d] + (uint32_t)p;
            if (FUSE) acc += fabsf(unflip(k) - init_sorted[g]);
            else      out[g] = k;
            if (PASS == 0)
                atomicAdd(&sm.h[warp & 3][(k >> 8) & 255u], 1u);
        }
        if (PASS == 1 || PASS == 2) {
            uint32_t d2 = (k >> (shift + 8)) & 255u;
            uint32_t vm = __ballot_sync(FULLMASK, v);
            uint32_t m  = __match_any_sync(FULLMASK, d2) & vm;
            if (v && lane == __ffs(m) - 1)
                atomicAdd(&sm.h[warp & 3][d2], (uint32_t)__popc(m));
        }
    }

    if (PASS < 3) {
        __syncthreads();
        if (tid < 256) {
            uint32_t v = sm.h[0][tid] + sm.h[1][tid] + sm.h[2][tid] + sm.h[3][tid];
            if (v) atomicAdd(&g_hist[s][PASS + 1][tid], v);
        }
        // make key writes + hist updates visible, then signal tile done
        __threadfence();
        __syncthreads();
        if (tid == 0) atomicAdd(&g_segdone[PASS][s], 1u);
    }

    if (FUSE) {
#pragma unroll
        for (int o = 16; o; o >>= 1) acc += __shfl_down_sync(FULLMASK, acc, o);
        if (lane == 0) sm.red[warp] = acc;
        __syncthreads();
        if (warp == 0) {
            float v = (lane < NWARP) ? sm.red[lane] : 0.f;
#pragma unroll
            for (int o = 8; o; o >>= 1) v += __shfl_down_sync(FULLMASK, v, o);
            if (lane == 0) g_part[b] = v;
        }
    }
}

// ---------------------------------------------------------------------------
// Persistent multi-pass driver: pass-major tickets; all dependencies are
// strictly-earlier tickets held by resident CTAs -> guaranteed progress.
__global__ __launch_bounds__(NT, 3) void k_sort(const float* __restrict__ x,
                                                const float* __restrict__ init) {
    __shared__ SortSmem sm;
    const int ntile = g_toff[NSEG];
    const int ntk   = 4 * ntile;
    for (;;) {
        if (threadIdx.x == 0) sm.tk = (int)atomicAdd(&g_ticket, 1u);
        __syncthreads();
        const int tk = sm.tk;
        if (tk >= ntk) return;
        const int pass = tk / ntile;
        const int b    = tk - pass * ntile;
        switch (pass) {
            case 0:  process_tile<0, false>(b, x, init, sm); break;
            case 1:  process_tile<1, false>(b, x, init, sm); break;
            case 2:  process_tile<2, false>(b, x, init, sm); break;
            default: process_tile<3, true >(b, x, init, sm); break;
        }
    }
}

// ---------------------------------------------------------------------------
__global__ void k_final(float* __restrict__ outp) {
    __shared__ float sh[256];
    int tid = threadIdx.x;
    float v = 0.f;
    if (tid < NSEG) {
        int len = g_off[tid + 1] - g_off[tid];
        float sum = 0.f;
        for (int t = g_toff[tid]; t < g_toff[tid + 1]; t++) sum += g_part[t];
        v = (len > 0) ? sum / (float)len : 0.f;
    }
    sh[tid] = v;
    __syncthreads();
    for (int o = 128; o; o >>= 1) {
        if (tid < o) sh[tid] += sh[tid + o];
        __syncthreads();
    }
    if (tid == 0) outp[0] = sh[0] * (1e-3f / (float)NSEG);
}

// ---------------------------------------------------------------------------
extern "C" void kernel_launch(void* const* d_in, const int* in_sizes, int n_in,
                              void* d_out, int out_size) {
    const float* x    = (const float*)d_in[0];
    const float* init = (const float*)d_in[1];
    const int*   seg  = (const int*)d_in[2];
    int n = in_sizes[0];

    k_setup<<<1, 256>>>(seg, n);
    k_zero<<<512, 512>>>();
    k_hist0<<<MAXT, NT>>>(x);
    k_sort<<<GRIDSORT, NT>>>(x, init);
    k_final<<<1, 256>>>((float*)d_out);
}

// round 10
// speedup vs baseline: 1.1497x; 1.1497x over previous
#include <cuda_runtime.h>
#include <stdint.h>

// EarthMoversDistanceRegularizer v9: persistent fused onesweep segmented LSD
// radix sort. v7 core (IT=8, atomic-return rank, plain inline histograms)
// + hist phase fused into the persistent kernel (phase 0 of 5, per-segment
// histdone gating) + release-atomic done signals instead of threadfence.

#define NSEG     200
#define NMAX     8388608
#define NT       512
#define NWARP    16
#define IT       8
#define TILE     (NT * IT)              // 4096
#define MAXT     2304                   // >= NMAX/TILE + NSEG = 2248
#define GRIDSORT 444                    // 148 SMs x 3 CTAs
#define FULLMASK 0xffffffffu
#define FLAGBIT  (1u << 30)
#define CNTMASK  0x3fffffffu

__device__ uint32_t g_keyA[NMAX];
__device__ uint32_t g_keyB[NMAX];
__device__ int      g_off[NSEG + 1];
__device__ int      g_toff[NSEG + 1];
__device__ int      g_tseg[MAXT];
__device__ uint32_t g_hist[NSEG][4][256];
__device__ uint32_t g_status[4][MAXT][256];
__device__ uint32_t g_histdone[NSEG];
__device__ uint32_t g_segdone[3][NSEG];
__device__ uint32_t g_ticket;
__device__ float    g_part[MAXT];

__device__ __forceinline__ uint32_t flipf(uint32_t u) {
    return (u & 0x80000000u) ? ~u : (u | 0x80000000u);
}
__device__ __forceinline__ float unflip(uint32_t k) {
    uint32_t u = (k & 0x80000000u) ? (k & 0x7fffffffu) : ~k;
    return __uint_as_float(u);
}
__device__ __forceinline__ void st_rlx(uint32_t* p, uint32_t v) {
    asm volatile("st.relaxed.gpu.u32 [%0], %1;" :: "l"(p), "r"(v) : "memory");
}
__device__ __forceinline__ uint32_t ld_rlx(const uint32_t* p) {
    uint32_t v;
    asm volatile("ld.relaxed.gpu.u32 %0, [%1];" : "=r"(v) : "l"(p) : "memory");
    return v;
}
__device__ __forceinline__ uint32_t ld_acq(const uint32_t* p) {
    uint32_t v;
    asm volatile("ld.acquire.gpu.u32 %0, [%1];" : "=r"(v) : "l"(p) : "memory");
    return v;
}
// Release add (no return). Cumulative: preceded by __syncthreads, it
// publishes the whole block's prior writes to a paired acquire reader.
__device__ __forceinline__ void red_release(uint32_t* p, uint32_t v) {
    asm volatile("red.release.gpu.global.add.u32 [%0], %1;" :: "l"(p), "r"(v)
                 : "memory");
}

struct SortSmem {
    uint32_t cnt[256][17];   // padded: conflict-free rank atomics + scan
    uint32_t exch[TILE];
    uint32_t loc[256];
    uint32_t fix[256];
    uint32_t wsum[8];
    uint32_t h[4][256];
    float    red[NWARP];
    int      tk;
};

// ---------------------------------------------------------------------------
// Exclusive prefix over values held by threads 0..255 (others pass 0).
__device__ __forceinline__ uint32_t scan256(uint32_t v, int tid, uint32_t* s_wsum) {
    int lane = tid & 31, w = tid >> 5;
    uint32_t inc = v;
#pragma unroll
    for (int o = 1; o < 32; o <<= 1) {
        uint32_t t = __shfl_up_sync(FULLMASK, inc, o);
        if (lane >= o) inc += t;
    }
    if (lane == 31 && w < 8) s_wsum[w] = inc;
    __syncthreads();
    if (w == 0 && lane < 8) {
        uint32_t x0 = s_wsum[lane];
        uint32_t i2 = x0;
#pragma unroll
        for (int o = 1; o < 8; o <<= 1) {
            uint32_t t = __shfl_up_sync(0xffu, i2, o);
            if (lane >= o) i2 += t;
        }
        s_wsum[lane] = i2 - x0;
    }
    __syncthreads();
    return inc - v + ((tid < 256) ? s_wsum[w] : 0u);
}

// ---------------------------------------------------------------------------
// Segment offsets (binary search) + tile offsets + tile->segment map.
__global__ void k_setup(const int* __restrict__ seg, int n) {
    __shared__ uint32_t s_wsum[8];
    int tid = threadIdx.x;
    if (tid <= NSEG) {
        int lo = 0, hi = n;
        while (lo < hi) {
            int mid = (lo + hi) >> 1;
            if (seg[mid] < tid) lo = mid + 1; else hi = mid;
        }
        g_off[tid] = lo;
    }
    __syncthreads();
    uint32_t nt = 0;
    if (tid < NSEG) {
        int len = g_off[tid + 1] - g_off[tid];
        nt = (uint32_t)((len + TILE - 1) / TILE);
    }
    uint32_t excl = scan256(nt, tid, s_wsum);
    if (tid <= NSEG) g_toff[tid] = (int)excl;
    for (int t = tid; t < MAXT; t += 256) g_tseg[t] = -1;
    __syncthreads();
    if (tid < NSEG)
        for (uint32_t t = 0; t < nt; t++) g_tseg[excl + t] = tid;
}

// ---------------------------------------------------------------------------
__global__ void k_zero() {
    const int gtid = blockIdx.x * blockDim.x + threadIdx.x;
    const int gstr = gridDim.x * blockDim.x;
    uint32_t* p = &g_status[0][0][0];
    for (int i = gtid; i < 4 * MAXT * 256; i += gstr) p[i] = 0;
    uint32_t* h = &g_hist[0][0][0];
    for (int i = gtid; i < NSEG * 4 * 256; i += gstr) h[i] = 0;
    uint32_t* d = &g_segdone[0][0];
    for (int i = gtid; i < 3 * NSEG; i += gstr) d[i] = 0;
    for (int i = gtid; i < NSEG; i += gstr) g_histdone[i] = 0;
    if (gtid == 0) g_ticket = 0;
}

// ---------------------------------------------------------------------------
// Phase 0: pass-0 (low byte) histogram for one tile. Low mantissa byte is
// ~uniform -> spread replicated smem atomics.
__device__ __forceinline__ void process_hist(int b, const float* __restrict__ x,
                                             SortSmem& sm) {
    const int s = g_tseg[b];
    const int tid = threadIdx.x, rep = (tid >> 5) & 3;
    const int t    = b - g_toff[s];
    const int tbeg = g_off[s] + t * TILE;
    const int tend = min(tbeg + TILE, g_off[s + 1]);

    for (int i = tid; i < 4 * 256; i += NT) ((uint32_t*)sm.h)[i] = 0;
    __syncthreads();
    for (int i = tbeg + tid; i < tend; i += NT)
        atomicAdd(&sm.h[rep][flipf(__float_as_uint(x[i])) & 255u], 1u);
    __syncthreads();
    if (tid < 256) {
        uint32_t v = sm.h[0][tid] + sm.h[1][tid] + sm.h[2][tid] + sm.h[3][tid];
        if (v) atomicAdd(&g_hist[s][0][tid], v);
    }
    __syncthreads();
    if (tid == 0) red_release(&g_histdone[s], 1u);
}

// ---------------------------------------------------------------------------
// One tile of one pass (called from the persistent k_sort).
template <int PASS, bool FUSE>
__device__ __forceinline__ void process_tile(int b,
                                             const float* __restrict__ xin,
                                             const float* __restrict__ init_sorted,
                                             SortSmem& sm) {
    const int s = g_tseg[b];
    const int tid = threadIdx.x, lane = tid & 31, warp = tid >> 5;
    const uint32_t lmask = (1u << lane) - 1u;

    const uint32_t* __restrict__ in =
        (PASS == 1 || PASS == 3) ? g_keyA : g_keyB;   // PASS0 unused
    uint32_t* __restrict__ out = (PASS & 1) ? g_keyB : g_keyA;
    const int shift = 8 * PASS;

    const int beg  = g_off[s], end = g_off[s + 1];
    const int t    = b - g_toff[s];
    const int tbeg = beg + t * TILE;
    const int tend = min(tbeg + TILE, end);
    const int vc   = tend - tbeg;

    // ---- gate: previous phase of this segment must be fully complete
    {
        if (tid == 0) {
            uint32_t need = (uint32_t)(g_toff[s + 1] - g_toff[s]);
            const uint32_t* gate = (PASS == 0) ? &g_histdone[s]
                                               : &g_segdone[PASS - 1][s];
            while (ld_acq(gate) < need) __nanosleep(64);
        }
        __syncthreads();
    }

    for (int i = tid; i < 256 * 17; i += NT) ((uint32_t*)sm.cnt)[i] = 0;
    if (PASS < 3)
        for (int i = tid; i < 4 * 256; i += NT) ((uint32_t*)sm.h)[i] = 0;
    __syncthreads();

    uint32_t keys[IT];
    uint32_t rnkp[IT / 2] = {0, 0, 0, 0};   // 2 x u16 ranks per word
    const int ibase = tbeg + warp * (IT * 32) + lane;

    if (vc == TILE) {
        // -------- fast path: every item valid
#pragma unroll
        for (int j = 0; j < IT; j++) {
            int idx = ibase + j * 32;
            keys[j] = (PASS == 0) ? flipf(__float_as_uint(xin[idx])) : in[idx];
        }
#pragma unroll
        for (int j = 0; j < IT; j++) {
            uint32_t d = (keys[j] >> shift) & 255u;
            uint32_t m = __match_any_sync(FULLMASK, d);
            int lead = __ffs(m) - 1;
            uint32_t cur = 0;
            if (lane == lead) cur = atomicAdd(&sm.cnt[d][warp], (uint32_t)__popc(m));
            cur = __shfl_sync(FULLMASK, cur, lead);
            rnkp[j >> 1] |= (cur + (uint32_t)__popc(m & lmask)) << (16 * (j & 1));
        }
    } else {
        // -------- tail tile: masked
#pragma unroll
        for (int j = 0; j < IT; j++) {
            int idx = ibase + j * 32;
            bool valid = idx < tend;
            keys[j] = valid ? ((PASS == 0) ? flipf(__float_as_uint(xin[idx]))
                                           : in[idx])
                            : 0u;
        }
#pragma unroll
        for (int j = 0; j < IT; j++) {
            bool valid = (ibase + j * 32) < tend;
            uint32_t d = (keys[j] >> shift) & 255u;
            uint32_t vm = __ballot_sync(FULLMASK, valid);
            uint32_t m  = __match_any_sync(FULLMASK, d) & vm;
            int lead = m ? (__ffs(m) - 1) : 0;
            uint32_t cur = 0;
            if (valid && lane == lead)
                cur = atomicAdd(&sm.cnt[d][warp], (uint32_t)__popc(m));
            cur = __shfl_sync(FULLMASK, cur, lead);
            rnkp[j >> 1] |= (cur + (uint32_t)__popc(m & lmask)) << (16 * (j & 1));
        }
    }
    __syncthreads();

    // ---- per-digit warp totals -> warp-exclusive in place; publish count
    uint32_t tot = 0;
    if (tid < 256) {
        uint32_t run = 0;
#pragma unroll
        for (int w = 0; w < NWARP; w++) {
            uint32_t c = sm.cnt[tid][w];
            sm.cnt[tid][w] = run;
            run += c;
        }
        tot = run;
        st_rlx(&g_status[PASS][b][tid], tot | FLAGBIT);   // unblock successors
    }

    // ---- packed scan: hi16 = tile-local digit start, lo16 = segment base
    // (cumulative tot <= 4096, cumulative hist <= seg len < 65536: no carry)
    uint32_t h = (tid < 256) ? g_hist[s][PASS][tid] : 0u;
    uint32_t px = scan256((tot << 16) | h, tid, sm.wsum);
    uint32_t loc  = px >> 16;
    uint32_t segx = px & 0xffffu;

    // ---- AGG-only lookback, 4-wide MLP batches
    if (tid < 256) {
        uint32_t excl = 0;
        int pt = b - 1;
        const int first = b - t;
        while (pt >= first) {
            int nb = min(4, pt - first + 1);
            uint32_t v0, v1 = 0, v2 = 0, v3 = 0;
            bool ok;
            do {
                v0 = ld_rlx(&g_status[PASS][pt][tid]);
                if (nb > 1) v1 = ld_rlx(&g_status[PASS][pt - 1][tid]);
                if (nb > 2) v2 = ld_rlx(&g_status[PASS][pt - 2][tid]);
                if (nb > 3) v3 = ld_rlx(&g_status[PASS][pt - 3][tid]);
                ok = (v0 != 0) && (nb < 2 || v1 != 0) &&
                     (nb < 3 || v2 != 0) && (nb < 4 || v3 != 0);
            } while (!ok);
            excl += (v0 & CNTMASK) + (v1 & CNTMASK) +
                    (v2 & CNTMASK) + (v3 & CNTMASK);
            pt -= nb;
        }
        sm.loc[tid] = loc;
        sm.fix[tid] = (uint32_t)beg + segx + excl - loc;
    }
    __syncthreads();

    // ---- scatter to smem exchange by tile-local rank
#pragma unroll
    for (int j = 0; j < IT; j++) {
        int idx = ibase + j * 32;
        if (idx < tend) {
            uint32_t d = (keys[j] >> shift) & 255u;
            uint32_t r = (rnkp[j >> 1] >> (16 * (j & 1))) & 0xffffu;
            sm.exch[sm.loc[d] + sm.cnt[d][warp] + r] = keys[j];
        }
    }
    __syncthreads();

    // ---- coalesced global pass; inline next-pass histogram (plain atomics)
    float acc = 0.f;
#pragma unroll
    for (int j = 0; j < IT; j++) {
        int p = j * NT + tid;
        if (p < vc) {
            uint32_t k = sm.exch[p];
            uint32_t d = (k >> shift) & 255u;
            uint32_t g = sm.fix[d] + (uint32_t)p;
            if (PASS < 3)
                atomicAdd(&sm.h[warp & 3][(k >> (shift + 8)) & 255u], 1u);
            if (FUSE) acc += fabsf(unflip(k) - init_sorted[g]);
            else      out[g] = k;
        }
    }

    if (PASS < 3) {
        __syncthreads();
        if (tid < 256) {
            uint32_t v = sm.h[0][tid] + sm.h[1][tid] + sm.h[2][tid] + sm.h[3][tid];
            if (v) atomicAdd(&g_hist[s][PASS + 1][tid], v);
        }
        // barrier orders the whole block's writes before the release-add
        __syncthreads();
        if (tid == 0) red_release(&g_segdone[PASS][s], 1u);
    }

    if (FUSE) {
#pragma unroll
        for (int o = 16; o; o >>= 1) acc += __shfl_down_sync(FULLMASK, acc, o);
        if (lane == 0) sm.red[warp] = acc;
        __syncthreads();
        if (warp == 0) {
            float v = (lane < NWARP) ? sm.red[lane] : 0.f;
#pragma unroll
            for (int o = 8; o; o >>= 1) v += __shfl_down_sync(FULLMASK, v, o);
            if (lane == 0) g_part[b] = v;
        }
    }
}

// ---------------------------------------------------------------------------
// Persistent driver: phase-major tickets (phase 0 = histogram, 1..4 = radix
// passes 0..3). All dependencies are strictly-earlier tickets held by
// resident CTAs -> guaranteed forward progress.
__global__ __launch_bounds__(NT, 3) void k_sort(const float* __restrict__ x,
                                                const float* __restrict__ init) {
    __shared__ SortSmem sm;
    const int ntile = g_toff[NSEG];
    const int ntk   = 5 * ntile;
    for (;;) {
        if (threadIdx.x == 0) sm.tk = (int)atomicAdd(&g_ticket, 1u);
        __syncthreads();
        const int tk = sm.tk;
        if (tk >= ntk) return;
        const int phase = tk / ntile;
        const int b     = tk - phase * ntile;
        switch (phase) {
            case 0:  process_hist(b, x, sm); break;
            case 1:  process_tile<0, false>(b, x, init, sm); break;
            case 2:  process_tile<1, false>(b, x, init, sm); break;
            case 3:  process_tile<2, false>(b, x, init, sm); break;
            default: process_tile<3, true >(b, x, init, sm); break;
        }
        __syncthreads();   // protect sm reuse across tickets
    }
}

// ---------------------------------------------------------------------------
__global__ void k_final(float* __restrict__ outp) {
    __shared__ float sh[256];
    int tid = threadIdx.x;
    float v = 0.f;
    if (tid < NSEG) {
        int len = g_off[tid + 1] - g_off[tid];
        float sum = 0.f;
        for (int t = g_toff[tid]; t < g_toff[tid + 1]; t++) sum += g_part[t];
        v = (len > 0) ? sum / (float)len : 0.f;
    }
    sh[tid] = v;
    __syncthreads();
    for (int o = 128; o; o >>= 1) {
        if (tid < o) sh[tid] += sh[tid + o];
        __syncthreads();
    }
    if (tid == 0) outp[0] = sh[0] * (1e-3f / (float)NSEG);
}

// ---------------------------------------------------------------------------
extern "C" void kernel_launch(void* const* d_in, const int* in_sizes, int n_in,
                              void* d_out, int out_size) {
    const float* x    = (const float*)d_in[0];
    const float* init = (const float*)d_in[1];
    const int*   seg  = (const int*)d_in[2];
    int n = in_sizes[0];

    k_setup<<<1, 256>>>(seg, n);
    k_zero<<<512, 512>>>();
    k_sort<<<GRIDSORT, NT>>>(x, init);
    k_final<<<1, 256>>>((float*)d_out);
}